// round 2
// baseline (speedup 1.0000x reference)
#include <cuda_runtime.h>
#include <stdint.h>
#include <math_constants.h>

#define K_CODES 8192
#define DIM     256
#define NTOK    32768
#define HW      1024

#define BM 128
#define BN 128
#define BK 16

// output layout (floats): loss | quantized | indices | new_count | new_weight | new_codebook
#define OUT_LOSS 0
#define OUT_Q    1
#define OUT_IDX  (OUT_Q  + 32*DIM*HW)
#define OUT_CNT  (OUT_IDX + NTOK)
#define OUT_W    (OUT_CNT + K_CODES)
#define OUT_CB   (OUT_W   + K_CODES*DIM)

// device scratch (no allocations allowed)
__device__ float              g_cbnorm[K_CODES];
__device__ float              g_znorm[NTOK];
__device__ unsigned long long g_best[NTOK];
__device__ float              g_counts[K_CODES];
__device__ float              g_dw[K_CODES * DIM];
__device__ double             g_loss;
__device__ int                g_idx[NTOK];

// ---------------- init ----------------
__global__ void init_kernel() {
    int i = blockIdx.x * blockDim.x + threadIdx.x;
    if (i < K_CODES * DIM) g_dw[i] = 0.0f;
    if (i < NTOK)          g_best[i] = 0xFFFFFFFFFFFFFFFFull;
    if (i < K_CODES)       g_counts[i] = 0.0f;
    if (i == 0)            g_loss = 0.0;
}

// ---------------- token norms ||z||^2 (fp64 accumulate -> fp32) ----------------
// token = b*1024 + hw; element d at x[b*DIM*HW + d*HW + hw]; coalesced across threads.
__global__ void znorm_kernel(const float* __restrict__ x) {
    int token = blockIdx.x * blockDim.x + threadIdx.x;
    int b = token >> 10, hw = token & 1023;
    const float* p = x + (size_t)b * DIM * HW + hw;
    double s = 0.0;
    #pragma unroll 8
    for (int d = 0; d < DIM; d++) {
        double v = (double)p[(size_t)d * HW];
        s = fma(v, v, s);
    }
    g_znorm[token] = (float)s;
}

// ---------------- codebook row norms (fp64 -> fp32) ----------------
__global__ void cbnorm_kernel(const float* __restrict__ cb) {
    int gt   = blockIdx.x * blockDim.x + threadIdx.x;
    int code = gt >> 5;
    int lane = gt & 31;
    if (code >= K_CODES) return;
    const float* r = cb + (size_t)code * DIM;
    double s = 0.0;
    #pragma unroll
    for (int i = lane; i < DIM; i += 32) {
        double v = (double)__ldg(r + i);
        s = fma(v, v, s);
    }
    #pragma unroll
    for (int o = 16; o; o >>= 1)
        s += __shfl_down_sync(0xFFFFFFFFu, s, o);
    if (lane == 0) g_cbnorm[code] = (float)s;
}

// ---------------- fused distance GEMM + reference-rounded argmin ----------------
__global__ void __launch_bounds__(256, 2)
gemm_argmin(const float* __restrict__ x, const float* __restrict__ cb) {
    __shared__ float As[BK][BM];
    __shared__ float Bs[BK][BN + 4];

    const int tb  = blockIdx.y;           // token tile (256 tiles)
    const int cbk = blockIdx.x;           // code tile (64 tiles)
    const int b   = (tb * BM) >> 10;
    const int hw0 = (tb * BM) & 1023;
    const float* xbase  = x  + (size_t)b * DIM * HW + hw0;
    const float* cbbase = cb + (size_t)cbk * BN * DIM;

    const int tid = threadIdx.x;
    float acc[8][8];
    #pragma unroll
    for (int i = 0; i < 8; i++)
        #pragma unroll
        for (int j = 0; j < 8; j++) acc[i][j] = 0.0f;

    const int trow = (tid >> 4) * 8;   // token sub-tile
    const int tcol = (tid & 15) * 8;   // code sub-tile

    for (int k0 = 0; k0 < DIM; k0 += BK) {
        {
            int d  = tid >> 4;            // 0..15
            int t4 = (tid & 15) * 8;      // 0..120
            const float4* src = (const float4*)(xbase + (size_t)(k0 + d) * HW + t4);
            float4 v0 = src[0];
            float4 v1 = src[1];
            *(float4*)&As[d][t4]     = v0;
            *(float4*)&As[d][t4 + 4] = v1;
        }
        {
            int cc = tid >> 1;            // 0..127
            int dp = (tid & 1) * 8;       // 0 or 8
            const float4* src = (const float4*)(cbbase + (size_t)cc * DIM + k0 + dp);
            float4 v0 = src[0];
            float4 v1 = src[1];
            Bs[dp + 0][cc] = v0.x; Bs[dp + 1][cc] = v0.y;
            Bs[dp + 2][cc] = v0.z; Bs[dp + 3][cc] = v0.w;
            Bs[dp + 4][cc] = v1.x; Bs[dp + 5][cc] = v1.y;
            Bs[dp + 6][cc] = v1.z; Bs[dp + 7][cc] = v1.w;
        }
        __syncthreads();

        #pragma unroll
        for (int kk = 0; kk < BK; kk++) {
            float a[8], bv[8];
            *(float4*)&a[0]  = *(float4*)&As[kk][trow];
            *(float4*)&a[4]  = *(float4*)&As[kk][trow + 4];
            *(float4*)&bv[0] = *(float4*)&Bs[kk][tcol];
            *(float4*)&bv[4] = *(float4*)&Bs[kk][tcol + 4];
            #pragma unroll
            for (int i = 0; i < 8; i++)
                #pragma unroll
                for (int j = 0; j < 8; j++)
                    acc[i][j] = fmaf(a[i], bv[j], acc[i][j]);
        }
        __syncthreads();
    }

    // epilogue replicating reference fp32 rounding:
    //   d = fl( fl(znorm + cnorm) - 2*dot )
    // then (d, idx) lexicographic min => first-index tie-break like jnp.argmin.
    const int token0 = tb * BM + trow;
    const int code0  = cbk * BN + tcol;
    float cn[8];
    #pragma unroll
    for (int j = 0; j < 8; j++) cn[j] = g_cbnorm[code0 + j];

    #pragma unroll
    for (int i = 0; i < 8; i++) {
        float zn = g_znorm[token0 + i];
        unsigned long long bestpk = 0xFFFFFFFFFFFFFFFFull;
        #pragma unroll
        for (int j = 0; j < 8; j++) {
            float t1 = __fadd_rn(zn, cn[j]);
            float d  = __fsub_rn(t1, __fmul_rn(2.0f, acc[i][j]));
            unsigned int e = __float_as_uint(d);
            e = (e & 0x80000000u) ? ~e : (e | 0x80000000u);  // order-preserving encode
            unsigned long long pk =
                ((unsigned long long)e << 32) | (unsigned int)(code0 + j);
            if (pk < bestpk) bestpk = pk;
        }
        atomicMin(&g_best[token0 + i], bestpk);
    }
}

// ---------------- extract indices, bump counts ----------------
__global__ void post_idx(float* __restrict__ out) {
    int n = blockIdx.x * blockDim.x + threadIdx.x;
    if (n >= NTOK) return;
    unsigned long long pk = g_best[n];
    int id = (int)(pk & 0xFFFFFFFFull);
    g_idx[n] = id;
    out[OUT_IDX + n] = (float)id;
    atomicAdd(&g_counts[id], 1.0f);
}

// ---------------- quantized output + commitment loss ----------------
__global__ void quant_loss(const float* __restrict__ x,
                           const float* __restrict__ cb,
                           float* __restrict__ out) {
    __shared__ float sred[256];
    int n = blockIdx.x;
    int c = threadIdx.x;
    int id = g_idx[n];
    float q = __ldg(cb + (size_t)id * DIM + c);
    int b = n >> 10, hw = n & 1023;
    size_t off = (size_t)b * DIM * HW + (size_t)c * HW + hw;
    float xv = x[off];
    out[OUT_Q + off] = __fadd_rn(xv, __fsub_rn(q, xv));  // straight-through, fp32 like jax
    float d = __fsub_rn(q, xv);
    sred[c] = d * d;
    __syncthreads();
    #pragma unroll
    for (int s = 128; s > 0; s >>= 1) {
        if (c < s) sred[c] += sred[c + s];
        __syncthreads();
    }
    if (c == 0) atomicAdd(&g_loss, (double)sred[0]);
}

// ---------------- dw = segment_sum(flat, idx) ----------------
__global__ void dw_kernel(const float* __restrict__ x) {
    int n = blockIdx.x * blockDim.x + threadIdx.x;
    int d = blockIdx.y;
    int b = n >> 10, hw = n & 1023;
    float v = x[(size_t)b * DIM * HW + (size_t)d * HW + hw];
    atomicAdd(&g_dw[(size_t)g_idx[n] * DIM + d], v);
}

// ---------------- EMA finalize ----------------
__global__ void final_kernel(const float* __restrict__ ema_count,
                             const float* __restrict__ ema_weight,
                             float* __restrict__ out) {
    int k = blockIdx.x;
    int c = threadIdx.x;
    float nc = ema_count[k] * 0.95f + 0.05f * g_counts[k];
    const float denom = (float)(32768.0 + 8192.0 * 1e-5);  // n + K*EPS
    nc = (nc + 1e-5f) / denom * 32768.0f;
    float w = ema_weight[(size_t)k * DIM + c] * 0.95f + 0.05f * g_dw[(size_t)k * DIM + c];
    out[OUT_W  + (size_t)k * DIM + c] = w;
    out[OUT_CB + (size_t)k * DIM + c] = w / nc;
    if (c == 0) out[OUT_CNT + k] = nc;
    if (k == 0 && c == 0) {
        double mean = g_loss / (double)((size_t)NTOK * DIM);
        out[OUT_LOSS] = 0.25f * (float)mean;
    }
}

extern "C" void kernel_launch(void* const* d_in, const int* in_sizes, int n_in,
                              void* d_out, int out_size) {
    const float* x          = (const float*)d_in[0];
    const float* cb         = (const float*)d_in[1];
    const float* ema_count  = (const float*)d_in[2];
    const float* ema_weight = (const float*)d_in[3];
    float* out = (float*)d_out;

    init_kernel<<<(K_CODES * DIM + 255) / 256, 256>>>();
    znorm_kernel<<<NTOK / 256, 256>>>(x);
    cbnorm_kernel<<<(K_CODES * 32 + 255) / 256, 256>>>(cb);
    gemm_argmin<<<dim3(K_CODES / BN, NTOK / BM), 256>>>(x, cb);
    post_idx<<<NTOK / 256, 256>>>(out);
    quant_loss<<<NTOK, 256>>>(x, cb, out);
    dw_kernel<<<dim3(NTOK / 256, DIM), 256>>>(x);
    final_kernel<<<K_CODES, DIM>>>(ema_count, ema_weight, out);
}